// round 8
// baseline (speedup 1.0000x reference)
#include <cuda_runtime.h>
#include <math.h>
#include <float.h>

constexpr int NMAX = 10000;
constexpr int EMAX = 50000;
constexpr int D    = 32;
constexpr int H    = 4;

// Scratch (no allocations allowed -> __device__ globals).
// INVARIANTS per launch:
//   g_denom : zeroed by a cudaMemsetAsync graph node before k_edge
//   g_agg   : zero at entry; read-then-zeroed by its sole reader (node warp)
//   g_ex    : fully overwritten each launch
__device__ float g_denom[NMAX * H];
__device__ float g_agg  [NMAX * D];
__device__ float g_ex   [EMAX * H];

__device__ __forceinline__ float warpSum32(float x) {
    #pragma unroll
    for (int off = 16; off; off >>= 1)
        x += __shfl_xor_sync(0xffffffffu, x, off);
    return x;
}

__device__ __forceinline__ float dot4(float4 a, float4 b) {
    return a.x*b.x + a.y*b.y + a.z*b.z + a.w*b.w;
}

__device__ __forceinline__ float sum8(const float* p) {
    float4 a = ((const float4*)p)[0];
    float4 b = ((const float4*)p)[1];
    return ((a.x + a.y) + (a.z + a.w)) + ((b.x + b.y) + (b.z + b.w));
}

// ---------------------------------------------------------------------------
// K1: per-edge hypernetwork K/V + logits + fused softmax-numerator work.
// One warp per edge, fully-coalesced weight loads via __ldcs.
// Partial row-dots go through a per-warp smem transpose (STS, conflict-free:
// store addr = 32*i + lane -> bank == lane) instead of shfl chains.
// ---------------------------------------------------------------------------
__global__ void __launch_bounds__(256) k_edge(
    const float* __restrict__ in_feat,
    const int*   __restrict__ src,
    const int*   __restrict__ dst,
    const float* __restrict__ skw,
    const float* __restrict__ dkw,
    const float* __restrict__ skb,
    const float* __restrict__ dkb,
    const float* __restrict__ svw,
    const float* __restrict__ dvw,
    const float* __restrict__ svb,
    const float* __restrict__ dvb,
    const float* __restrict__ query,
    float* __restrict__ key_out,
    float* __restrict__ val_out,
    int E)
{
    const int gw   = blockIdx.x * 8 + (threadIdx.x >> 5);
    const int lane = threadIdx.x & 31;
    const int wl   = threadIdx.x >> 5;
    // partial[row][chunk] per warp: 32 rows x 8 chunks
    __shared__ __align__(16) float kpart[8][32][8];
    __shared__ __align__(16) float vpart[8][32][8];
    if (gw >= E) return;
    const int e = gw;
    const int s = src[e];
    const int d = dst[e];

    const float4* inf4 = (const float4*)in_feat;
    const int c = lane & 7;
    const int r = lane >> 3;
    const float4 u4 = inf4[(long)s * 8 + c];
    const float4 v4 = inf4[(long)d * 8 + c];

    const float4* A  = (const float4*)skw + (long)e * 256;
    const float4* B  = (const float4*)dkw + (long)e * 256;
    const float4* Cw = (const float4*)svw + (long)e * 256;
    const float4* Dw = (const float4*)dvw + (long)e * 256;

    #pragma unroll
    for (int i = 0; i < 8; i++) {
        const int idx = i * 32 + lane;
        float4 a  = __ldcs(A  + idx);
        float4 b  = __ldcs(B  + idx);
        float4 cc = __ldcs(Cw + idx);
        float4 dd = __ldcs(Dw + idx);
        const int row = i * 4 + r;
        kpart[wl][row][c] = dot4(a, u4) + dot4(b, v4);
        vpart[wl][row][c] = dot4(cc, u4) + dot4(dd, v4);
    }
    __syncwarp();

    const long eo = (long)e * 32 + lane;
    float kacc = sum8(kpart[wl][lane]) + __ldcs(skb + eo) + __ldcs(dkb + eo);
    float vacc = sum8(vpart[wl][lane]) + __ldcs(svb + eo) + __ldcs(dvb + eo);
    key_out[eo] = kacc;
    val_out[eo] = vacc;

    // logits: per-head dot K[h,:] . query[dst][h,:] (8-lane groups).
    float p = kacc * query[(long)d * D + lane];
    p += __shfl_xor_sync(0xffffffffu, p, 1);
    p += __shfl_xor_sync(0xffffffffu, p, 2);
    p += __shfl_xor_sync(0xffffffffu, p, 4);

    // exp(logit): exact softmax without max-shift (logits are O(1))
    const float ex = expf(p);
    atomicAdd(&g_agg[d * D + lane], vacc * ex);
    if ((lane & 7) == 0) {
        const int h = lane >> 3;
        g_ex[e * H + h] = ex;
        atomicAdd(&g_denom[d * H + h], ex);
    }
}

// ---------------------------------------------------------------------------
// K2 (fused tail):
//  attn blocks: one THREAD per edge, float4 loads/stores.
//  node blocks: GEMV (smem-partial reduction, no shfl) + relu + residual +
//               layernorm; restores g_agg to zero (sole reader).
// ---------------------------------------------------------------------------
__global__ void __launch_bounds__(256) k_tail(
    const int*   __restrict__ dst,
    float* __restrict__ attn_out,
    const float* __restrict__ in_feat,
    const float* __restrict__ node_w,
    const float* __restrict__ node_b,
    const float* __restrict__ ln_w,
    const float* __restrict__ ln_b,
    float* __restrict__ out,
    int N, int E, int attnBlocks)
{
    if ((int)blockIdx.x < attnBlocks) {
        const int e = blockIdx.x * blockDim.x + threadIdx.x;
        if (e >= E) return;
        const int d = dst[e];
        const float4 ex4 = ((const float4*)g_ex)[e];
        const float4 dn  = *(const float4*)(g_denom + d * H);
        float4 at;
        at.x = ex4.x / dn.x;
        at.y = ex4.y / dn.y;
        at.z = ex4.z / dn.z;
        at.w = ex4.w / dn.w;
        ((float4*)attn_out)[e] = at;
        return;
    }

    // ---- node: warp per node ----
    const int lane = threadIdx.x & 31;
    const int wl   = threadIdx.x >> 5;
    const int n    = ((int)blockIdx.x - attnBlocks) * 8 + wl;
    __shared__ __align__(16) float sa[8][D];
    __shared__ __align__(16) float part[8][32][8];
    if (n >= N) return;

    const float nb  = node_b[(long)n * D + lane];
    const float inf = in_feat[(long)n * D + lane];
    const float lw  = ln_w[lane];
    const float lb  = ln_b[lane];
    const float den = g_denom[n * H + (lane >> 3)];
    const float agv = g_agg[n * D + lane];
    __syncwarp();                       // reads done before restore
    g_agg[n * D + lane] = 0.0f;         // restore invariant

    float a = (den > 0.0f) ? (agv / den) : 0.0f;
    sa[wl][lane] = a;
    __syncwarp();

    const int c = lane & 7;
    const int r = lane >> 3;
    const float4 x4 = ((const float4*)sa[wl])[c];

    const float4* W = (const float4*)node_w + (long)n * 256;
    #pragma unroll
    for (int i = 0; i < 8; i++) {
        float4 w = __ldcs(W + i * 32 + lane);
        part[wl][i * 4 + r][c] = dot4(w, x4);
    }
    __syncwarp();

    float acc = fmaxf(sum8(part[wl][lane]) + nb, 0.0f);

    float x = inf + acc;
    float mu = warpSum32(x) * (1.0f / 32.0f);
    float xm = x - mu;
    float var = warpSum32(xm * xm) * (1.0f / 32.0f);
    float y = xm * rsqrtf(var + 1e-5f) * lw + lb;
    out[(long)n * D + lane] = y;
}

// ---------------------------------------------------------------------------
extern "C" void kernel_launch(void* const* d_in, const int* in_sizes, int n_in,
                              void* d_out, int out_size) {
    const float* in_feat = (const float*)d_in[0];
    const int*   src     = (const int*)  d_in[1];
    const int*   dst     = (const int*)  d_in[2];
    const float* skw     = (const float*)d_in[3];
    const float* dkw     = (const float*)d_in[4];
    const float* skb     = (const float*)d_in[5];
    const float* dkb     = (const float*)d_in[6];
    const float* svw     = (const float*)d_in[7];
    const float* dvw     = (const float*)d_in[8];
    const float* svb     = (const float*)d_in[9];
    const float* dvb     = (const float*)d_in[10];
    const float* query   = (const float*)d_in[11];
    const float* node_w  = (const float*)d_in[12];
    const float* node_b  = (const float*)d_in[13];
    const float* ln_w    = (const float*)d_in[14];
    const float* ln_b    = (const float*)d_in[15];

    const int N = in_sizes[0] / D;   // 10000
    const int E = in_sizes[1];       // 50000

    float* out_ptr  = (float*)d_out;
    float* key_ptr  = out_ptr + (long)N * D;
    float* val_ptr  = key_ptr + (long)E * D;
    float* attn_ptr = val_ptr + (long)E * D;

    // zero g_denom via a memset graph node (cheaper than a kernel launch)
    void* denom_ptr = nullptr;
    cudaGetSymbolAddress(&denom_ptr, g_denom);
    cudaMemsetAsync(denom_ptr, 0, NMAX * H * sizeof(float));

    const int attnBlocks = (E + 255) / 256;       // one THREAD per edge
    const int nodeBlocks = (N + 7) / 8;

    k_edge<<<(E + 7) / 8, 256>>>(in_feat, src, dst, skw, dkw, skb, dkb,
                                 svw, dvw, svb, dvb, query,
                                 key_ptr, val_ptr, E);
    k_tail<<<attnBlocks + nodeBlocks, 256>>>(dst, attn_ptr, in_feat,
                                             node_w, node_b, ln_w, ln_b,
                                             out_ptr, N, E, attnBlocks);
}

// round 9
// speedup vs baseline: 1.0167x; 1.0167x over previous
#include <cuda_runtime.h>
#include <math.h>
#include <float.h>

constexpr int NMAX = 10000;
constexpr int EMAX = 50000;
constexpr int D    = 32;
constexpr int H    = 4;

// Scratch (no allocations allowed -> __device__ globals).
// INVARIANTS per launch:
//   g_denom : zeroed by a cudaMemsetAsync graph node before k_edge
//   g_agg   : zero at entry; read-then-zeroed by its sole reader (node warp)
//   g_ex    : fully overwritten each launch
__device__ float g_denom[NMAX * H];
__device__ float g_agg  [NMAX * D];
__device__ float g_ex   [EMAX * H];

__device__ __forceinline__ float warpSum32(float x) {
    #pragma unroll
    for (int off = 16; off; off >>= 1)
        x += __shfl_xor_sync(0xffffffffu, x, off);
    return x;
}

__device__ __forceinline__ float dot4(float4 a, float4 b) {
    return a.x*b.x + a.y*b.y + a.z*b.z + a.w*b.w;
}

// ---------------------------------------------------------------------------
// K1: per-edge hypernetwork K/V + logits + fused softmax-numerator work.
//   ex = exp(logit) (no max subtraction; exact, logits are O(1))
//   denom[d,h] += ex ;  agg[d,:] += V*ex   (atomics, avg 5 edges/node)
// One warp per edge, fully-coalesced weight loads via __ldcs (read-once).
// Lane holds (row=4i+lane/8, chunk=lane%8); row-dot reduced over the 8-lane
// group via shfl_xor.  [round-6 verified-best version]
// ---------------------------------------------------------------------------
__global__ void __launch_bounds__(256) k_edge(
    const float* __restrict__ in_feat,
    const int*   __restrict__ src,
    const int*   __restrict__ dst,
    const float* __restrict__ skw,
    const float* __restrict__ dkw,
    const float* __restrict__ skb,
    const float* __restrict__ dkb,
    const float* __restrict__ svw,
    const float* __restrict__ dvw,
    const float* __restrict__ svb,
    const float* __restrict__ dvb,
    const float* __restrict__ query,
    float* __restrict__ key_out,
    float* __restrict__ val_out,
    int E)
{
    const int gw   = blockIdx.x * 8 + (threadIdx.x >> 5);
    const int lane = threadIdx.x & 31;
    const int wl   = threadIdx.x >> 5;
    __shared__ float kbuf[8][32];
    __shared__ float vbuf[8][32];
    if (gw >= E) return;
    const int e = gw;
    const int s = src[e];
    const int d = dst[e];

    const float4* inf4 = (const float4*)in_feat;
    const int c = lane & 7;
    const float4 u4 = inf4[(long)s * 8 + c];
    const float4 v4 = inf4[(long)d * 8 + c];

    const float4* A  = (const float4*)skw + (long)e * 256;
    const float4* B  = (const float4*)dkw + (long)e * 256;
    const float4* Cw = (const float4*)svw + (long)e * 256;
    const float4* Dw = (const float4*)dvw + (long)e * 256;

    #pragma unroll
    for (int i = 0; i < 8; i++) {
        const int idx = i * 32 + lane;
        float4 a  = __ldcs(A  + idx);
        float4 b  = __ldcs(B  + idx);
        float4 cc = __ldcs(Cw + idx);
        float4 dd = __ldcs(Dw + idx);
        float pk = dot4(a, u4) + dot4(b, v4);
        float pv = dot4(cc, u4) + dot4(dd, v4);
        pk += __shfl_xor_sync(0xffffffffu, pk, 1);
        pv += __shfl_xor_sync(0xffffffffu, pv, 1);
        pk += __shfl_xor_sync(0xffffffffu, pk, 2);
        pv += __shfl_xor_sync(0xffffffffu, pv, 2);
        pk += __shfl_xor_sync(0xffffffffu, pk, 4);
        pv += __shfl_xor_sync(0xffffffffu, pv, 4);
        if (c == 0) {
            const int row = i * 4 + (lane >> 3);
            kbuf[wl][row] = pk;
            vbuf[wl][row] = pv;
        }
    }
    __syncwarp();

    const long eo = (long)e * 32 + lane;
    float kacc = kbuf[wl][lane] + __ldcs(skb + eo) + __ldcs(dkb + eo);
    float vacc = vbuf[wl][lane] + __ldcs(svb + eo) + __ldcs(dvb + eo);
    key_out[eo] = kacc;
    val_out[eo] = vacc;

    // logits: per-head dot K[h,:] . query[dst][h,:] (8-lane groups).
    float p = kacc * query[(long)d * D + lane];
    p += __shfl_xor_sync(0xffffffffu, p, 1);
    p += __shfl_xor_sync(0xffffffffu, p, 2);
    p += __shfl_xor_sync(0xffffffffu, p, 4);

    const float ex = expf(p);
    atomicAdd(&g_agg[d * D + lane], vacc * ex);
    if ((lane & 7) == 0) {
        const int h = lane >> 3;
        g_ex[e * H + h] = ex;
        atomicAdd(&g_denom[d * H + h], ex);
    }
}

// ---------------------------------------------------------------------------
// K2 (fused tail):
//  attn blocks: one THREAD per edge, float4 loads/stores.
//  node blocks: GEMV with w[8] register preload (MLP=8) + shfl reduction +
//               relu + residual + layernorm; restores g_agg (sole reader).
//  [round-5/6 verified-best node branch]
// ---------------------------------------------------------------------------
__global__ void __launch_bounds__(256) k_tail(
    const int*   __restrict__ dst,
    float* __restrict__ attn_out,
    const float* __restrict__ in_feat,
    const float* __restrict__ node_w,
    const float* __restrict__ node_b,
    const float* __restrict__ ln_w,
    const float* __restrict__ ln_b,
    float* __restrict__ out,
    int N, int E, int attnBlocks)
{
    if ((int)blockIdx.x < attnBlocks) {
        const int e = blockIdx.x * blockDim.x + threadIdx.x;
        if (e >= E) return;
        const int d = dst[e];
        const float4 ex4 = ((const float4*)g_ex)[e];
        const float4 dn  = *(const float4*)(g_denom + d * H);
        float4 at;
        at.x = ex4.x / dn.x;
        at.y = ex4.y / dn.y;
        at.z = ex4.z / dn.z;
        at.w = ex4.w / dn.w;
        ((float4*)attn_out)[e] = at;
        return;
    }

    // ---- node: warp per node ----
    const int lane = threadIdx.x & 31;
    const int wl   = threadIdx.x >> 5;
    const int n    = ((int)blockIdx.x - attnBlocks) * 8 + wl;
    __shared__ __align__(16) float sa[8][D];
    __shared__ float obuf[8][32];
    if (n >= N) return;

    // batch independent loads up-front: 8x node_w float4 (MLP=8) + scalars
    const float4* W = (const float4*)node_w + (long)n * 256 + lane;
    float4 w[8];
    #pragma unroll
    for (int i = 0; i < 8; i++) w[i] = __ldcs(W + i * 32);

    const float nb  = node_b[(long)n * D + lane];
    const float inf = in_feat[(long)n * D + lane];
    const float lw  = ln_w[lane];
    const float lb  = ln_b[lane];
    const float den = g_denom[n * H + (lane >> 3)];
    const float agv = g_agg[n * D + lane];
    __syncwarp();                       // all reads done before restore
    g_agg[n * D + lane] = 0.0f;         // restore invariant for next launch

    float a = (den > 0.0f) ? (agv / den) : 0.0f;
    sa[wl][lane] = a;
    __syncwarp();

    const int c = lane & 7;
    const float4 x4 = ((const float4*)sa[wl])[c];

    #pragma unroll
    for (int i = 0; i < 8; i++) {
        float p = dot4(w[i], x4);
        p += __shfl_xor_sync(0xffffffffu, p, 1);
        p += __shfl_xor_sync(0xffffffffu, p, 2);
        p += __shfl_xor_sync(0xffffffffu, p, 4);
        if (c == 0) obuf[wl][i * 4 + (lane >> 3)] = p;
    }
    __syncwarp();

    float acc = fmaxf(obuf[wl][lane] + nb, 0.0f);

    float x = inf + acc;
    float mu = warpSum32(x) * (1.0f / 32.0f);
    float xm = x - mu;
    float var = warpSum32(xm * xm) * (1.0f / 32.0f);
    float y = xm * rsqrtf(var + 1e-5f) * lw + lb;
    out[(long)n * D + lane] = y;
}

// ---------------------------------------------------------------------------
extern "C" void kernel_launch(void* const* d_in, const int* in_sizes, int n_in,
                              void* d_out, int out_size) {
    const float* in_feat = (const float*)d_in[0];
    const int*   src     = (const int*)  d_in[1];
    const int*   dst     = (const int*)  d_in[2];
    const float* skw     = (const float*)d_in[3];
    const float* dkw     = (const float*)d_in[4];
    const float* skb     = (const float*)d_in[5];
    const float* dkb     = (const float*)d_in[6];
    const float* svw     = (const float*)d_in[7];
    const float* dvw     = (const float*)d_in[8];
    const float* svb     = (const float*)d_in[9];
    const float* dvb     = (const float*)d_in[10];
    const float* query   = (const float*)d_in[11];
    const float* node_w  = (const float*)d_in[12];
    const float* node_b  = (const float*)d_in[13];
    const float* ln_w    = (const float*)d_in[14];
    const float* ln_b    = (const float*)d_in[15];

    const int N = in_sizes[0] / D;   // 10000
    const int E = in_sizes[1];       // 50000

    float* out_ptr  = (float*)d_out;
    float* key_ptr  = out_ptr + (long)N * D;
    float* val_ptr  = key_ptr + (long)E * D;
    float* attn_ptr = val_ptr + (long)E * D;

    // zero g_denom via a memset graph node (cheaper than a kernel launch)
    void* denom_ptr = nullptr;
    cudaGetSymbolAddress(&denom_ptr, g_denom);
    cudaMemsetAsync(denom_ptr, 0, NMAX * H * sizeof(float));

    const int attnBlocks = (E + 255) / 256;       // one THREAD per edge
    const int nodeBlocks = (N + 7) / 8;

    k_edge<<<(E + 7) / 8, 256>>>(in_feat, src, dst, skw, dkw, skb, dkb,
                                 svw, dvw, svb, dvb, query,
                                 key_ptr, val_ptr, E);
    k_tail<<<attnBlocks + nodeBlocks, 256>>>(dst, attn_ptr, in_feat,
                                             node_w, node_b, ln_w, ln_b,
                                             out_ptr, N, E, attnBlocks);
}